// round 15
// baseline (speedup 1.0000x reference)
#include <cuda_runtime.h>
#include <math.h>

#define L_SEQ   2048
#define D_IN    1024
#define N_ST    16
#define BATCH   2
#define NTOK    (BATCH * L_SEQ)      // 4096
#define NCHUNK  128
#define CLEN    16                   // L_SEQ / NCHUNK
#define NSEG    8
#define SEGLEN  16                   // NCHUNK / NSEG
#define KSPLIT  4
#define LOG2E   1.4426950408889634f

typedef unsigned long long ull;

// ------------------------------- scratch ----------------------------------
__device__ float g_part [KSPLIT * NTOK * 64];              // split-K partials
__device__ float g_delta[NTOK * D_IN];                     // (tok, d)
__device__ float g_bc   [NTOK * 32];                       // (tok, n)  n<16:B, n>=16:C
__device__ float g_sd   [BATCH * D_IN * NCHUNK];
__device__ float g_hloc [BATCH * D_IN * NCHUNK * N_ST];
__device__ float g_hin  [BATCH * D_IN * NCHUNK * N_ST];

__device__ __forceinline__ float ex2f(float x) {
    float r; asm("ex2.approx.ftz.f32 %0, %1;" : "=f"(r) : "f"(x)); return r;
}
// fast softplus: max(z,0) + log(1+e^-|z|) with MUFU exp/log.
__device__ __forceinline__ float softplusf(float z) {
    return fmaxf(z, 0.0f) + __logf(1.0f + __expf(-fabsf(z)));
}
__device__ __forceinline__ ull packf2(float lo, float hi) {
    ull d; asm("mov.b64 %0, {%1, %2};" : "=l"(d) : "r"(__float_as_uint(lo)), "r"(__float_as_uint(hi)));
    return d;
}
__device__ __forceinline__ void unpackf2(float& lo, float& hi, ull v) {
    unsigned a, b; asm("mov.b64 {%0, %1}, %2;" : "=r"(a), "=r"(b) : "l"(v));
    lo = __uint_as_float(a); hi = __uint_as_float(b);
}
__device__ __forceinline__ ull fma2(ull a, ull b, ull c) {
    ull d; asm("fma.rn.f32x2 %0, %1, %2, %3;" : "=l"(d) : "l"(a), "l"(b), "l"(c));
    return d;
}
__device__ __forceinline__ ull mul2(ull a, ull b) {
    ull d; asm("mul.rn.f32x2 %0, %1, %2;" : "=l"(d) : "l"(a), "l"(b));
    return d;
}
__device__ __forceinline__ ull add2(ull a, ull b) {
    ull d; asm("add.rn.f32x2 %0, %1, %2;" : "=l"(d) : "l"(a), "l"(b));
    return d;
}

// ------------------ K1a: stage-1 GEMM, split-K(4), k-pair f32x2 -------------
__global__ __launch_bounds__(128) void k1a_gemm(
    const float* __restrict__ x,      // (4096, 1024)
    const float* __restrict__ w1)     // (64, 1024)
{
    __shared__ __align__(16) float xs[64][68];
    __shared__ __align__(16) float ws[64][68];

    const int tid = threadIdx.x;
    const int tg = blockIdx.x & 63, ks = blockIdx.x >> 6;
    const int tokbase = tg * 64;
    const int kbase = ks * 256;
    const int ct = tid & 7, tt = tid >> 3;

    ull acc[4][8];
#pragma unroll
    for (int i = 0; i < 4; i++)
#pragma unroll
        for (int j = 0; j < 8; j++) acc[i][j] = 0ull;

#pragma unroll 1
    for (int kt = 0; kt < 4; kt++) {
        const int k0 = kbase + kt * 64;
#pragma unroll
        for (int r = 0; r < 8; r++) {
            int f = tid + r * 128;               // 1024 float4 = 64 rows x 16
            int row = f >> 4, c4 = f & 15;
            *(float4*)&xs[row][c4 * 4] =
                *(const float4*)&x[(size_t)(tokbase + row) * D_IN + k0 + c4 * 4];
        }
#pragma unroll
        for (int r = 0; r < 8; r++) {
            int f = tid + r * 128;
            int row = f >> 4, c4 = f & 15;
            *(float4*)&ws[row][c4 * 4] =
                *(const float4*)&w1[(size_t)row * D_IN + k0 + c4 * 4];
        }
        __syncthreads();

#pragma unroll 8
        for (int kp = 0; kp < 32; kp++) {
            ull xv[4], wv[8];
#pragma unroll
            for (int i = 0; i < 4; i++) xv[i] = *(const ull*)&xs[tt + 16 * i][2 * kp];
#pragma unroll
            for (int j = 0; j < 8; j++) wv[j] = *(const ull*)&ws[ct + 8 * j][2 * kp];
#pragma unroll
            for (int i = 0; i < 4; i++)
#pragma unroll
                for (int j = 0; j < 8; j++)
                    acc[i][j] = fma2(xv[i], wv[j], acc[i][j]);
        }
        __syncthreads();
    }

#pragma unroll
    for (int i = 0; i < 4; i++)
#pragma unroll
        for (int j = 0; j < 8; j++) {
            float lo, hi; unpackf2(lo, hi, acc[i][j]);
            xs[tt + 16 * i][ct + 8 * j] = lo + hi;
        }
    __syncthreads();
#pragma unroll
    for (int r = 0; r < 8; r++) {
        int f = tid + r * 128;                   // 1024 f4 = 64 rows x 16
        int row = f >> 4, c4 = f & 15;
        *(float4*)&g_part[((size_t)ks * NTOK + tokbase + row) * 64 + c4 * 4] =
            *(float4*)&xs[row][c4 * 4];
    }
}

// --- K1b fused: partials -> delta GEMM + two 16-step chunk scans per block ---
// 1024 blocks = 128 token-groups(32 tok = 2 chunks) x 8 d-groups(128 d).
__global__ __launch_bounds__(128) void k1b_fused(
    const float* __restrict__ x,      // (4096, 1024)
    const float* __restrict__ dtw,    // (1024, 32)
    const float* __restrict__ bias,   // (1024)
    const float* __restrict__ gs,     // (B, L)
    const float* __restrict__ gcw,    // (16)
    const float* __restrict__ gcb,    // (16)
    const float* __restrict__ gCw,    // scalar
    const float* __restrict__ alogs)  // (1024, 16)
{
    __shared__ __align__(16) float xd[32][36];
    __shared__ __align__(16) float dw[128][34];   // stride 34: 2-way max on LDS.64
    __shared__ __align__(16) float sB[32][16];
    __shared__ float sX[CLEN][128];               // per-half x buffer

    const int tid = threadIdx.x;
    const int dg = blockIdx.x & 7, tg = blockIdx.x >> 3;
    const int tokbase = tg * 32;
    const int b  = tokbase >> 11;
    const int chbase = (tokbase & 2047) >> 4;     // first chunk of this group
    const int d  = dg * 128 + tid;

    // ---- gather: split-K sums for dts_r ----
#pragma unroll
    for (int r = 0; r < 2; r++) {
        int f = tid + r * 128;                   // 256 f4 = 32 rows x 8
        int row = f >> 3, c4 = f & 7;
        float4 s = make_float4(0.f, 0.f, 0.f, 0.f);
#pragma unroll
        for (int k = 0; k < KSPLIT; k++) {
            float4 v = *(const float4*)&g_part[((size_t)k * NTOK + tokbase + row) * 64 + c4 * 4];
            s.x += v.x; s.y += v.y; s.z += v.z; s.w += v.w;
        }
        *(float4*)&xd[row][c4 * 4] = s;
    }
#pragma unroll
    for (int r = 0; r < 16; r++) {
        int f = tid + r * 128;                   // 2048 float2 = 128 rows x 16
        int row = f >> 4, c2 = f & 15;
        *(float2*)&dw[row][c2 * 2] =
            *(const float2*)&dtw[(size_t)(dg * 128 + row) * 32 + c2 * 2];
    }
    // B tile straight from partials (B needs no gradient correction)
#pragma unroll
    for (int i = 0; i < 4; i++) {
        int idx = tid + i * 128;                 // 512 = 32 s x 16 n
        int s = idx >> 4, n = idx & 15;
        float v = 0.f;
#pragma unroll
        for (int k = 0; k < KSPLIT; k++)
            v += g_part[((size_t)k * NTOK + tokbase + s) * 64 + 32 + n];
        sB[s][n] = v;
    }
    // dg==0 blocks emit B and corrected C to gmem (consumed by k4)
    if (dg == 0) {
        const float gCwv = gCw[0];
#pragma unroll
        for (int r = 0; r < 8; r++) {
            int f = tid + r * 128;               // 1024 = 32 tok x 32 n
            int t = f >> 5, n = f & 31;
            float s = 0.f;
#pragma unroll
            for (int k = 0; k < KSPLIT; k++)
                s += g_part[((size_t)k * NTOK + tokbase + t) * 64 + 32 + n];
            int tok = tokbase + t;
            int l = tok & 2047;
            if (n >= 16) {
                int m = n - 16;
                s += gCwv * (gs[b * 2048 + m * 128 + (l >> 4)] * gcw[l & 15] + gcb[l & 15]);
            }
            g_bc[(size_t)tok * 32 + n] = s;
        }
    }
    __syncthreads();

    // ---- fused delta-dot + two chunk scans (delta also stored for k4) ----
    ull w2r[16];
    const ull* wrow = (const ull*)&dw[tid][0];
#pragma unroll
    for (int k = 0; k < 16; k++) w2r[k] = wrow[k];
    const float bz = bias[d];

    float cn[16];
#pragma unroll
    for (int n = 0; n < 16; n++)
        cn[n] = -__expf(alogs[(size_t)d * 16 + n]) * LOG2E;
    bool fast = true;
#pragma unroll
    for (int n = 1; n < 16; n++) {
        float want = (float)(n + 1) * cn[0];
        fast = fast && (fabsf(cn[n] - want) <= 1e-4f * fabsf(want));
    }

    float* dltout = &g_delta[(size_t)tokbase * D_IN + d];
    const float* xp = &x[(size_t)tokbase * D_IN + d];
    if (fast) {
        const float c0 = cn[0];
#pragma unroll 1
        for (int half = 0; half < 2; half++) {
            const int t0 = half * CLEN;
            const size_t base = (size_t)(b * 1024 + d) * NCHUNK + chbase + half;
            // own-column x prefetch of this chunk (no barrier: same-thread STS->LDS)
#pragma unroll
            for (int s = 0; s < CLEN; s++)
                sX[s][tid] = xp[(size_t)(t0 + s) * D_IN];
            float sd = 0.f;
            ull h2[8];
#pragma unroll
            for (int k = 0; k < 8; k++) h2[k] = 0ull;
#pragma unroll 8
            for (int s = 0; s < CLEN; s++) {
                const int t = t0 + s;
                const ulonglong2* xrow = (const ulonglong2*)&xd[t][0];   // broadcast
                ull a2 = 0ull, b2 = 0ull;
#pragma unroll
                for (int k = 0; k < 8; k++) {
                    ulonglong2 qv = xrow[k];
                    a2 = fma2(w2r[2 * k],     qv.x, a2);
                    b2 = fma2(w2r[2 * k + 1], qv.y, b2);
                }
                float lo, hi; unpackf2(lo, hi, add2(a2, b2));
                float dv = softplusf(lo + hi + bz);
                sd += dv;
                dltout[(size_t)t * D_IN] = dv;
                float xv = sX[s][tid];
                float e  = ex2f(dv * c0);
                float e2 = e * e;
                float u  = dv * xv;
                ull uu = packf2(u, u);
                ull dd = packf2(e2, e2);
                ull pp = packf2(e, e2);
                const ulonglong2* B2 = (const ulonglong2*)&sB[t][0];
                ulonglong2 b0 = B2[0], b1 = B2[1], b2v = B2[2], b3 = B2[3];
                h2[0] = fma2(pp, h2[0], mul2(uu, b0.x)); pp = mul2(pp, dd);
                h2[1] = fma2(pp, h2[1], mul2(uu, b0.y)); pp = mul2(pp, dd);
                h2[2] = fma2(pp, h2[2], mul2(uu, b1.x)); pp = mul2(pp, dd);
                h2[3] = fma2(pp, h2[3], mul2(uu, b1.y)); pp = mul2(pp, dd);
                h2[4] = fma2(pp, h2[4], mul2(uu, b2v.x)); pp = mul2(pp, dd);
                h2[5] = fma2(pp, h2[5], mul2(uu, b2v.y)); pp = mul2(pp, dd);
                h2[6] = fma2(pp, h2[6], mul2(uu, b3.x)); pp = mul2(pp, dd);
                h2[7] = fma2(pp, h2[7], mul2(uu, b3.y));
            }
            g_sd[base] = sd;
#pragma unroll
            for (int k = 0; k < 8; k++) *(ull*)&g_hloc[base * 16 + 2 * k] = h2[k];
        }
    } else {
#pragma unroll 1
        for (int half = 0; half < 2; half++) {
            const int t0 = half * CLEN;
            const size_t base = (size_t)(b * 1024 + d) * NCHUNK + chbase + half;
#pragma unroll
            for (int s = 0; s < CLEN; s++)
                sX[s][tid] = xp[(size_t)(t0 + s) * D_IN];
            float sd = 0.f;
            float h[16];
#pragma unroll
            for (int n = 0; n < 16; n++) h[n] = 0.f;
#pragma unroll 4
            for (int s = 0; s < CLEN; s++) {
                const int t = t0 + s;
                float a = bz;
#pragma unroll
                for (int k = 0; k < 32; k++) a += dw[tid][k] * xd[t][k];
                float dv = softplusf(a);
                sd += dv;
                dltout[(size_t)t * D_IN] = dv;
                float xv = sX[s][tid];
                float u = dv * xv;
#pragma unroll
                for (int n = 0; n < 16; n++) {
                    float av = ex2f(dv * cn[n]);
                    h[n] = av * h[n] + u * sB[t][n];
                }
            }
            g_sd[base] = sd;
#pragma unroll
            for (int n = 0; n < 16; n++) g_hloc[base * 16 + n] = h[n];
        }
    }
}

// ------------- K3: hierarchical combine (seg fold / scan / replay) ----------
// 2048 blocks = (b,d). 128 threads = (n:16, seg:8). Depth 16+8+16.
__global__ __launch_bounds__(128) void k3_combine(const float* __restrict__ alogs)
{
    __shared__ float ssd  [NSEG];
    __shared__ float sHseg[NSEG][16];
    __shared__ float sCar [NSEG][16];

    const int tid = threadIdx.x;
    const int n = tid & 15;
    const int seg = tid >> 4;
    const int bd = blockIdx.x;                 // b*1024 + d
    const int d = bd & 1023;
    const float cnf = -__expf(alogs[(size_t)d * 16 + n]) * LOG2E;
    const size_t base = (size_t)bd * NCHUNK + seg * SEGLEN;

    float sd[SEGLEN], hl[SEGLEN];
#pragma unroll
    for (int j = 0; j < SEGLEN; j++) {
        sd[j] = g_sd[base + j];
        hl[j] = g_hloc[(base + j) * 16 + n];
    }
    float H = 0.f, S = 0.f;
#pragma unroll
    for (int j = 0; j < SEGLEN; j++) {
        H = ex2f(sd[j] * cnf) * H + hl[j];
        S += sd[j];
    }
    sHseg[seg][n] = H;
    if (n == 0) ssd[seg] = S;
    __syncthreads();

    if (tid < 16) {
        float Hc = 0.f;
#pragma unroll
        for (int s = 0; s < NSEG; s++) {
            sCar[s][tid] = Hc;
            Hc = ex2f(ssd[s] * cnf) * Hc + sHseg[s][tid];
        }
    }
    __syncthreads();

    H = sCar[seg][n];
#pragma unroll
    for (int j = 0; j < SEGLEN; j++) {
        g_hin[(base + j) * 16 + n] = H;
        H = ex2f(sd[j] * cnf) * H + hl[j];
    }
}

// --------- K4: phase 3 (emit y), 16-step chunks, 2048 blocks ---------------
__global__ __launch_bounds__(128, 8) void k4_phase3(
    const float* __restrict__ x, const float* __restrict__ alogs,
    const float* __restrict__ Ds, float* __restrict__ y)
{
    __shared__ __align__(16) float sB[CLEN][16];
    __shared__ __align__(16) float sC[CLEN][16];
    __shared__ float sD[CLEN][128];
    __shared__ float sX[CLEN][128];
    const int tid = threadIdx.x;
    const int bid = blockIdx.x;
    const int ch = bid & (NCHUNK - 1);
    const int dg = (bid >> 7) & 7;
    const int b  = bid >> 10;
    const int d  = dg * 128 + tid;
    const int l0 = ch * CLEN;

    {
        int s = tid >> 3, qd = tid & 7;          // 16 rows x 8 float4
        float4 v = *(const float4*)&g_bc[(size_t)(b * 2048 + l0 + s) * 32 + qd * 4];
        if (qd < 4) ((float4*)&sB[s][0])[qd] = v;
        else        ((float4*)&sC[s][0])[qd - 4] = v;
    }
    __syncthreads();     // protects sB/sC only; before the prefetch

    const size_t base = (size_t)(b * 1024 + d) * NCHUNK + ch;
    ull h2[8];
#pragma unroll
    for (int k = 0; k < 8; k++) h2[k] = *(const ull*)&g_hin[base * 16 + 2 * k];

    const float* dlt = &g_delta[(size_t)(b * 2048 + l0) * D_IN + d];
    const float* xp  = &x[(size_t)(b * 2048 + l0) * D_IN + d];
#pragma unroll
    for (int s = 0; s < CLEN; s++) {
        sD[s][tid] = dlt[(size_t)s * D_IN];
        sX[s][tid] = xp[(size_t)s * D_IN];
    }

    float cn[16];
#pragma unroll
    for (int n = 0; n < 16; n++)
        cn[n] = -__expf(alogs[(size_t)d * 16 + n]) * LOG2E;
    bool fast = true;
#pragma unroll
    for (int n = 1; n < 16; n++) {
        float want = (float)(n + 1) * cn[0];
        fast = fast && (fabsf(cn[n] - want) <= 1e-4f * fabsf(want));
    }

    const float dsv = Ds[d];
    float* yp = &y[(size_t)(b * 2048 + l0) * D_IN + d];

    if (fast) {
        const float c0 = cn[0];
#pragma unroll 4
        for (int s = 0; s < CLEN; s++) {
            float dv = sD[s][tid];
            float xv = sX[s][tid];
            float e  = ex2f(dv * c0);
            float e2 = e * e;
            float u  = dv * xv;
            ull uu = packf2(u, u);
            ull dd = packf2(e2, e2);
            ull pp = packf2(e, e2);
            const ulonglong2* B2 = (const ulonglong2*)&sB[s][0];
            const ulonglong2* C2 = (const ulonglong2*)&sC[s][0];
            ulonglong2 b0 = B2[0], b1 = B2[1], b2v = B2[2], b3 = B2[3];
            ulonglong2 cc0 = C2[0], cc1 = C2[1], cc2 = C2[2], cc3 = C2[3];
            ull y2a, y2b;
            h2[0] = fma2(pp, h2[0], mul2(uu, b0.x));  y2a = mul2(h2[0], cc0.x); pp = mul2(pp, dd);
            h2[1] = fma2(pp, h2[1], mul2(uu, b0.y));  y2b = mul2(h2[1], cc0.y); pp = mul2(pp, dd);
            h2[2] = fma2(pp, h2[2], mul2(uu, b1.x));  y2a = fma2(h2[2], cc1.x, y2a); pp = mul2(pp, dd);
            h2[3] = fma2(pp, h2[3], mul2(uu, b1.y));  y2b = fma2(h2[3], cc1.y, y2b); pp = mul2(pp, dd);
            h2[4] = fma2(pp, h2[4], mul2(uu, b2v.x)); y2a = fma2(h2[4], cc2.x, y2a); pp = mul2(pp, dd);
            h2[5] = fma2(pp, h2[5], mul2(uu, b2v.y)); y2b = fma2(h2[5], cc2.y, y2b); pp = mul2(pp, dd);
            h2[6] = fma2(pp, h2[6], mul2(uu, b3.x));  y2a = fma2(h2[6], cc3.x, y2a); pp = mul2(pp, dd);
            h2[7] = fma2(pp, h2[7], mul2(uu, b3.y));  y2b = fma2(h2[7], cc3.y, y2b);
            float ylo, yhi; unpackf2(ylo, yhi, add2(y2a, y2b));
            yp[(size_t)s * D_IN] = ylo + yhi + xv * dsv;
        }
    } else {
        float h[16];
#pragma unroll
        for (int n = 0; n < 16; n++) { float lo, hi; unpackf2(lo, hi, h2[n >> 1]); h[n] = (n & 1) ? hi : lo; }
        for (int s = 0; s < CLEN; s++) {
            float dv = sD[s][tid];
            float xv = sX[s][tid];
            float u = dv * xv;
            float y0 = 0.f, y1 = 0.f;
#pragma unroll
            for (int n = 0; n < 16; n++) {
                float a = ex2f(dv * cn[n]);
                h[n] = a * h[n] + u * sB[s][n];
                if (n & 1) y1 += h[n] * sC[s][n];
                else       y0 += h[n] * sC[s][n];
            }
            yp[(size_t)s * D_IN] = y0 + y1 + xv * dsv;
        }
    }
}

// ------------------------------- launcher ----------------------------------
extern "C" void kernel_launch(void* const* d_in, const int* in_sizes, int n_in,
                              void* d_out, int out_size)
{
    const float* x     = (const float*)d_in[0];
    const float* gs    = (const float*)d_in[1];
    const float* w1    = (const float*)d_in[2];
    const float* dtw   = (const float*)d_in[3];
    const float* bias  = (const float*)d_in[4];
    const float* alogs = (const float*)d_in[5];
    const float* Ds    = (const float*)d_in[6];
    const float* gcw   = (const float*)d_in[7];
    const float* gcb   = (const float*)d_in[8];
    const float* gCw   = (const float*)d_in[9];
    float* y = (float*)d_out;

    k1a_gemm <<<64 * KSPLIT, 128>>>(x, w1);
    k1b_fused<<<128 * 8, 128>>>(x, dtw, bias, gs, gcw, gcb, gCw, alogs);
    k3_combine<<<BATCH * D_IN, 128>>>(alogs);
    k4_phase3<<<BATCH * 8 * NCHUNK, 128>>>(x, alogs, Ds, y);
}

// round 16
// speedup vs baseline: 1.2059x; 1.2059x over previous
#include <cuda_runtime.h>
#include <math.h>

#define L_SEQ   2048
#define D_IN    1024
#define N_ST    16
#define BATCH   2
#define NTOK    (BATCH * L_SEQ)      // 4096
#define NCHUNK  64
#define CLEN    32                   // L_SEQ / NCHUNK
#define HCLEN   16                   // CLEN / 2 (two-phase prefetch length)
#define NSEG    8
#define SEGLEN  8                    // NCHUNK / NSEG
#define KSPLIT  4
#define LOG2E   1.4426950408889634f

typedef unsigned long long ull;

// ------------------------------- scratch ----------------------------------
__device__ float g_part [KSPLIT * NTOK * 64];              // split-K partials
__device__ float g_delta[NTOK * D_IN];                     // (tok, d)
__device__ float g_bc   [NTOK * 32];                       // (tok, n)  n<16:B, n>=16:C
__device__ float g_sd   [BATCH * D_IN * NCHUNK];
__device__ float g_hloc [BATCH * D_IN * NCHUNK * N_ST];
__device__ float g_hin  [BATCH * D_IN * NCHUNK * N_ST];

__device__ __forceinline__ float ex2f(float x) {
    float r; asm("ex2.approx.ftz.f32 %0, %1;" : "=f"(r) : "f"(x)); return r;
}
// fast softplus: max(z,0) + log(1+e^-|z|) with MUFU exp/log.
__device__ __forceinline__ float softplusf(float z) {
    return fmaxf(z, 0.0f) + __logf(1.0f + __expf(-fabsf(z)));
}
__device__ __forceinline__ ull packf2(float lo, float hi) {
    ull d; asm("mov.b64 %0, {%1, %2};" : "=l"(d) : "r"(__float_as_uint(lo)), "r"(__float_as_uint(hi)));
    return d;
}
__device__ __forceinline__ void unpackf2(float& lo, float& hi, ull v) {
    unsigned a, b; asm("mov.b64 {%0, %1}, %2;" : "=r"(a), "=r"(b) : "l"(v));
    lo = __uint_as_float(a); hi = __uint_as_float(b);
}
__device__ __forceinline__ ull fma2(ull a, ull b, ull c) {
    ull d; asm("fma.rn.f32x2 %0, %1, %2, %3;" : "=l"(d) : "l"(a), "l"(b), "l"(c));
    return d;
}
__device__ __forceinline__ ull mul2(ull a, ull b) {
    ull d; asm("mul.rn.f32x2 %0, %1, %2;" : "=l"(d) : "l"(a), "l"(b));
    return d;
}
__device__ __forceinline__ ull add2(ull a, ull b) {
    ull d; asm("add.rn.f32x2 %0, %1, %2;" : "=l"(d) : "l"(a), "l"(b));
    return d;
}

// ------------------ K1a: stage-1 GEMM, split-K(4), k-pair f32x2 -------------
__global__ __launch_bounds__(128) void k1a_gemm(
    const float* __restrict__ x,      // (4096, 1024)
    const float* __restrict__ w1)     // (64, 1024)
{
    __shared__ __align__(16) float xs[64][68];
    __shared__ __align__(16) float ws[64][68];

    const int tid = threadIdx.x;
    const int tg = blockIdx.x & 63, ks = blockIdx.x >> 6;
    const int tokbase = tg * 64;
    const int kbase = ks * 256;
    const int ct = tid & 7, tt = tid >> 3;

    ull acc[4][8];
#pragma unroll
    for (int i = 0; i < 4; i++)
#pragma unroll
        for (int j = 0; j < 8; j++) acc[i][j] = 0ull;

#pragma unroll 1
    for (int kt = 0; kt < 4; kt++) {
        const int k0 = kbase + kt * 64;
#pragma unroll
        for (int r = 0; r < 8; r++) {
            int f = tid + r * 128;               // 1024 float4 = 64 rows x 16
            int row = f >> 4, c4 = f & 15;
            *(float4*)&xs[row][c4 * 4] =
                *(const float4*)&x[(size_t)(tokbase + row) * D_IN + k0 + c4 * 4];
        }
#pragma unroll
        for (int r = 0; r < 8; r++) {
            int f = tid + r * 128;
            int row = f >> 4, c4 = f & 15;
            *(float4*)&ws[row][c4 * 4] =
                *(const float4*)&w1[(size_t)row * D_IN + k0 + c4 * 4];
        }
        __syncthreads();

#pragma unroll 8
        for (int kp = 0; kp < 32; kp++) {
            ull xv[4], wv[8];
#pragma unroll
            for (int i = 0; i < 4; i++) xv[i] = *(const ull*)&xs[tt + 16 * i][2 * kp];
#pragma unroll
            for (int j = 0; j < 8; j++) wv[j] = *(const ull*)&ws[ct + 8 * j][2 * kp];
#pragma unroll
            for (int i = 0; i < 4; i++)
#pragma unroll
                for (int j = 0; j < 8; j++)
                    acc[i][j] = fma2(xv[i], wv[j], acc[i][j]);
        }
        __syncthreads();
    }

#pragma unroll
    for (int i = 0; i < 4; i++)
#pragma unroll
        for (int j = 0; j < 8; j++) {
            float lo, hi; unpackf2(lo, hi, acc[i][j]);
            xs[tt + 16 * i][ct + 8 * j] = lo + hi;
        }
    __syncthreads();
#pragma unroll
    for (int r = 0; r < 8; r++) {
        int f = tid + r * 128;                   // 1024 f4 = 64 rows x 16
        int row = f >> 4, c4 = f & 15;
        *(float4*)&g_part[((size_t)ks * NTOK + tokbase + row) * 64 + c4 * 4] =
            *(float4*)&xs[row][c4 * 4];
    }
}

// --- K1b fused: partials -> (delta GEMM + phase-1 scan) fused, delta stored ---
// 1024 blocks = 128 token-groups(=chunks, 32 tok) x 8 d-groups(128 d).
__global__ __launch_bounds__(128) void k1b_fused(
    const float* __restrict__ x,      // (4096, 1024)
    const float* __restrict__ dtw,    // (1024, 32)
    const float* __restrict__ bias,   // (1024)
    const float* __restrict__ gs,     // (B, L)
    const float* __restrict__ gcw,    // (16)
    const float* __restrict__ gcb,    // (16)
    const float* __restrict__ gCw,    // scalar
    const float* __restrict__ alogs)  // (1024, 16)
{
    __shared__ __align__(16) float xd[32][36];
    __shared__ __align__(16) float dw[128][34];   // stride 34: 2-way max on LDS.64
    __shared__ __align__(16) float sB[CLEN][16];
    __shared__ float sX[HCLEN][128];              // two-phase x buffer

    const int tid = threadIdx.x;
    const int dg = blockIdx.x & 7, tg = blockIdx.x >> 3;
    const int tokbase = tg * 32;
    const int b  = tokbase >> 11;
    const int ch = (tokbase & 2047) >> 5;         // chunk index within batch
    const int d  = dg * 128 + tid;

    // ---- gather: split-K sums for dts_r ----
#pragma unroll
    for (int r = 0; r < 2; r++) {
        int f = tid + r * 128;                   // 256 f4 = 32 rows x 8
        int row = f >> 3, c4 = f & 7;
        float4 s = make_float4(0.f, 0.f, 0.f, 0.f);
#pragma unroll
        for (int k = 0; k < KSPLIT; k++) {
            float4 v = *(const float4*)&g_part[((size_t)k * NTOK + tokbase + row) * 64 + c4 * 4];
            s.x += v.x; s.y += v.y; s.z += v.z; s.w += v.w;
        }
        *(float4*)&xd[row][c4 * 4] = s;
    }
#pragma unroll
    for (int r = 0; r < 16; r++) {
        int f = tid + r * 128;                   // 2048 float2 = 128 rows x 16
        int row = f >> 4, c2 = f & 15;
        *(float2*)&dw[row][c2 * 2] =
            *(const float2*)&dtw[(size_t)(dg * 128 + row) * 32 + c2 * 2];
    }
    // B tile straight from partials (B needs no gradient correction)
#pragma unroll
    for (int i = 0; i < 4; i++) {
        int idx = tid + i * 128;                 // 512 = 32 s x 16 n
        int s = idx >> 4, n = idx & 15;
        float v = 0.f;
#pragma unroll
        for (int k = 0; k < KSPLIT; k++)
            v += g_part[((size_t)k * NTOK + tokbase + s) * 64 + 32 + n];
        sB[s][n] = v;
    }
    // dg==0 blocks emit B and corrected C to gmem (consumed by k4)
    if (dg == 0) {
        const float gCwv = gCw[0];
#pragma unroll
        for (int r = 0; r < 8; r++) {
            int f = tid + r * 128;               // 1024 = 32 tok x 32 n
            int t = f >> 5, n = f & 31;
            float s = 0.f;
#pragma unroll
            for (int k = 0; k < KSPLIT; k++)
                s += g_part[((size_t)k * NTOK + tokbase + t) * 64 + 32 + n];
            int tok = tokbase + t;
            int l = tok & 2047;
            if (n >= 16) {
                int m = n - 16;
                s += gCwv * (gs[b * 2048 + m * 128 + (l >> 4)] * gcw[l & 15] + gcb[l & 15]);
            }
            g_bc[(size_t)tok * 32 + n] = s;
        }
    }
    __syncthreads();

    // ---- fused delta-dot + phase-1 chunk scan (delta also stored for k4) ----
    ull w2r[16];
    const ull* wrow = (const ull*)&dw[tid][0];
#pragma unroll
    for (int k = 0; k < 16; k++) w2r[k] = wrow[k];
    const float bz = bias[d];

    float cn[16];
#pragma unroll
    for (int n = 0; n < 16; n++)
        cn[n] = -__expf(alogs[(size_t)d * 16 + n]) * LOG2E;
    bool fast = true;
#pragma unroll
    for (int n = 1; n < 16; n++) {
        float want = (float)(n + 1) * cn[0];
        fast = fast && (fabsf(cn[n] - want) <= 1e-4f * fabsf(want));
    }

    float* dltout = &g_delta[(size_t)tokbase * D_IN + d];
    const float* xp = &x[(size_t)tokbase * D_IN + d];
    const size_t base = (size_t)(b * 1024 + d) * NCHUNK + ch;
    float sd = 0.f;
    if (fast) {
        const float c0 = cn[0];
        ull h2[8];
#pragma unroll
        for (int k = 0; k < 8; k++) h2[k] = 0ull;
#pragma unroll 1
        for (int half = 0; half < 2; half++) {
            const int t0 = half * HCLEN;
            // own-column x prefetch of this half (no barrier: same-thread STS->LDS)
#pragma unroll
            for (int s = 0; s < HCLEN; s++)
                sX[s][tid] = xp[(size_t)(t0 + s) * D_IN];
#pragma unroll 8
            for (int s = 0; s < HCLEN; s++) {
                const int t = t0 + s;
                const ulonglong2* xrow = (const ulonglong2*)&xd[t][0];   // broadcast
                ull a2 = 0ull, b2 = 0ull;
#pragma unroll
                for (int k = 0; k < 8; k++) {
                    ulonglong2 qv = xrow[k];
                    a2 = fma2(w2r[2 * k],     qv.x, a2);
                    b2 = fma2(w2r[2 * k + 1], qv.y, b2);
                }
                float lo, hi; unpackf2(lo, hi, add2(a2, b2));
                float dv = softplusf(lo + hi + bz);
                sd += dv;
                dltout[(size_t)t * D_IN] = dv;
                float xv = sX[s][tid];
                float e  = ex2f(dv * c0);
                float e2 = e * e;
                float u  = dv * xv;
                ull uu = packf2(u, u);
                ull dd = packf2(e2, e2);
                ull pp = packf2(e, e2);
                const ulonglong2* B2 = (const ulonglong2*)&sB[t][0];
                ulonglong2 b0 = B2[0], b1 = B2[1], b2v = B2[2], b3 = B2[3];
                h2[0] = fma2(pp, h2[0], mul2(uu, b0.x)); pp = mul2(pp, dd);
                h2[1] = fma2(pp, h2[1], mul2(uu, b0.y)); pp = mul2(pp, dd);
                h2[2] = fma2(pp, h2[2], mul2(uu, b1.x)); pp = mul2(pp, dd);
                h2[3] = fma2(pp, h2[3], mul2(uu, b1.y)); pp = mul2(pp, dd);
                h2[4] = fma2(pp, h2[4], mul2(uu, b2v.x)); pp = mul2(pp, dd);
                h2[5] = fma2(pp, h2[5], mul2(uu, b2v.y)); pp = mul2(pp, dd);
                h2[6] = fma2(pp, h2[6], mul2(uu, b3.x)); pp = mul2(pp, dd);
                h2[7] = fma2(pp, h2[7], mul2(uu, b3.y));
            }
        }
        g_sd[base] = sd;
#pragma unroll
        for (int k = 0; k < 8; k++) *(ull*)&g_hloc[base * 16 + 2 * k] = h2[k];
    } else {
        float h[16];
#pragma unroll
        for (int n = 0; n < 16; n++) h[n] = 0.f;
#pragma unroll 1
        for (int half = 0; half < 2; half++) {
            const int t0 = half * HCLEN;
#pragma unroll
            for (int s = 0; s < HCLEN; s++)
                sX[s][tid] = xp[(size_t)(t0 + s) * D_IN];
#pragma unroll 4
            for (int s = 0; s < HCLEN; s++) {
                const int t = t0 + s;
                float a = bz;
#pragma unroll
                for (int k = 0; k < 32; k++) a += dw[tid][k] * xd[t][k];
                float dv = softplusf(a);
                sd += dv;
                dltout[(size_t)t * D_IN] = dv;
                float xv = sX[s][tid];
                float u = dv * xv;
#pragma unroll
                for (int n = 0; n < 16; n++) {
                    float av = ex2f(dv * cn[n]);
                    h[n] = av * h[n] + u * sB[t][n];
                }
            }
        }
        g_sd[base] = sd;
#pragma unroll
        for (int n = 0; n < 16; n++) g_hloc[base * 16 + n] = h[n];
    }
}

// ------------- K3: hierarchical combine (seg fold / scan / replay) ----------
__global__ __launch_bounds__(128) void k3_combine(const float* __restrict__ alogs)
{
    __shared__ float ssd  [NSEG];
    __shared__ float sHseg[NSEG][16];
    __shared__ float sCar [NSEG][16];

    const int tid = threadIdx.x;
    const int n = tid & 15;
    const int seg = tid >> 4;
    const int bd = blockIdx.x;                 // b*1024 + d
    const int d = bd & 1023;
    const float cnf = -__expf(alogs[(size_t)d * 16 + n]) * LOG2E;
    const size_t base = (size_t)bd * NCHUNK + seg * SEGLEN;

    float sd[SEGLEN], hl[SEGLEN];
#pragma unroll
    for (int j = 0; j < SEGLEN; j++) {
        sd[j] = g_sd[base + j];
        hl[j] = g_hloc[(base + j) * 16 + n];
    }
    float H = 0.f, S = 0.f;
#pragma unroll
    for (int j = 0; j < SEGLEN; j++) {
        H = ex2f(sd[j] * cnf) * H + hl[j];
        S += sd[j];
    }
    sHseg[seg][n] = H;
    if (n == 0) ssd[seg] = S;
    __syncthreads();

    if (tid < 16) {
        float Hc = 0.f;
#pragma unroll
        for (int s = 0; s < NSEG; s++) {
            sCar[s][tid] = Hc;
            Hc = ex2f(ssd[s] * cnf) * Hc + sHseg[s][tid];
        }
    }
    __syncthreads();

    H = sCar[seg][n];
#pragma unroll
    for (int j = 0; j < SEGLEN; j++) {
        g_hin[(base + j) * 16 + n] = H;
        H = ex2f(sd[j] * cnf) * H + hl[j];
    }
}

// --------- K4: phase 3 (emit y), dg-fastest grid, hoisted h2 loads ----------
__global__ __launch_bounds__(128, 8) void k4_phase3(
    const float* __restrict__ x, const float* __restrict__ alogs,
    const float* __restrict__ Ds, float* __restrict__ y)
{
    __shared__ __align__(16) float sB[CLEN][16];
    __shared__ __align__(16) float sC[CLEN][16];
    __shared__ float sD[HCLEN][128];
    __shared__ float sX[HCLEN][128];
    const int tid = threadIdx.x;
    const int bid = blockIdx.x;
    const int dg = bid & 7;                      // fastest: 8 CTAs share g_bc chunk
    const int ch = (bid >> 3) & (NCHUNK - 1);
    const int b  = bid >> 9;
    const int d  = dg * 128 + tid;
    const int l0 = ch * CLEN;

    // hoisted: h2 loads issue before smem staging (overlap DRAM latency)
    const size_t base = (size_t)(b * 1024 + d) * NCHUNK + ch;
    ull h2[8];
#pragma unroll
    for (int k = 0; k < 8; k++) h2[k] = *(const ull*)&g_hin[base * 16 + 2 * k];

#pragma unroll
    for (int i = 0; i < 2; i++) {
        int idx = tid + i * 128;
        int s = idx >> 3, qd = idx & 7;
        float4 v = *(const float4*)&g_bc[(size_t)(b * 2048 + l0 + s) * 32 + qd * 4];
        if (qd < 4) ((float4*)&sB[s][0])[qd] = v;
        else        ((float4*)&sC[s][0])[qd - 4] = v;
    }
    __syncthreads();     // protects sB/sC only; before the prefetch

    const float* dlt = &g_delta[(size_t)(b * 2048 + l0) * D_IN + d];
    const float* xp  = &x[(size_t)(b * 2048 + l0) * D_IN + d];

    float cn[16];
#pragma unroll
    for (int n = 0; n < 16; n++)
        cn[n] = -__expf(alogs[(size_t)d * 16 + n]) * LOG2E;
    bool fast = true;
#pragma unroll
    for (int n = 1; n < 16; n++) {
        float want = (float)(n + 1) * cn[0];
        fast = fast && (fabsf(cn[n] - want) <= 1e-4f * fabsf(want));
    }

    const float dsv = Ds[d];
    float* yp = &y[(size_t)(b * 2048 + l0) * D_IN + d];

    if (fast) {
        const float c0 = cn[0];
#pragma unroll 1
        for (int half = 0; half < 2; half++) {
            const int s0 = half * HCLEN;
            // own-column prefetch of this half (no barrier: same-thread STS->LDS)
#pragma unroll
            for (int s = 0; s < HCLEN; s++) {
                sD[s][tid] = dlt[(size_t)(s0 + s) * D_IN];
                sX[s][tid] = xp[(size_t)(s0 + s) * D_IN];
            }
#pragma unroll 4
            for (int s = 0; s < HCLEN; s++) {
                float dv = sD[s][tid];
                float xv = sX[s][tid];
                float e  = ex2f(dv * c0);
                float e2 = e * e;
                float u  = dv * xv;
                ull uu = packf2(u, u);
                ull dd = packf2(e2, e2);
                ull pp = packf2(e, e2);
                const ulonglong2* B2 = (const ulonglong2*)&sB[s0 + s][0];
                const ulonglong2* C2 = (const ulonglong2*)&sC[s0 + s][0];
                ulonglong2 b0 = B2[0], b1 = B2[1], b2v = B2[2], b3 = B2[3];
                ulonglong2 cc0 = C2[0], cc1 = C2[1], cc2 = C2[2], cc3 = C2[3];
                ull y2a, y2b;
                h2[0] = fma2(pp, h2[0], mul2(uu, b0.x));  y2a = mul2(h2[0], cc0.x); pp = mul2(pp, dd);
                h2[1] = fma2(pp, h2[1], mul2(uu, b0.y));  y2b = mul2(h2[1], cc0.y); pp = mul2(pp, dd);
                h2[2] = fma2(pp, h2[2], mul2(uu, b1.x));  y2a = fma2(h2[2], cc1.x, y2a); pp = mul2(pp, dd);
                h2[3] = fma2(pp, h2[3], mul2(uu, b1.y));  y2b = fma2(h2[3], cc1.y, y2b); pp = mul2(pp, dd);
                h2[4] = fma2(pp, h2[4], mul2(uu, b2v.x)); y2a = fma2(h2[4], cc2.x, y2a); pp = mul2(pp, dd);
                h2[5] = fma2(pp, h2[5], mul2(uu, b2v.y)); y2b = fma2(h2[5], cc2.y, y2b); pp = mul2(pp, dd);
                h2[6] = fma2(pp, h2[6], mul2(uu, b3.x));  y2a = fma2(h2[6], cc3.x, y2a); pp = mul2(pp, dd);
                h2[7] = fma2(pp, h2[7], mul2(uu, b3.y));  y2b = fma2(h2[7], cc3.y, y2b);
                float ylo, yhi; unpackf2(ylo, yhi, add2(y2a, y2b));
                yp[(size_t)(s0 + s) * D_IN] = ylo + yhi + xv * dsv;
            }
        }
    } else {
        float h[16];
#pragma unroll
        for (int n = 0; n < 16; n++) { float lo, hi; unpackf2(lo, hi, h2[n >> 1]); h[n] = (n & 1) ? hi : lo; }
#pragma unroll 1
        for (int half = 0; half < 2; half++) {
            const int s0 = half * HCLEN;
#pragma unroll
            for (int s = 0; s < HCLEN; s++) {
                sD[s][tid] = dlt[(size_t)(s0 + s) * D_IN];
                sX[s][tid] = xp[(size_t)(s0 + s) * D_IN];
            }
            for (int s = 0; s < HCLEN; s++) {
                float dv = sD[s][tid];
                float xv = sX[s][tid];
                float u = dv * xv;
                float y0 = 0.f, y1 = 0.f;
#pragma unroll
                for (int n = 0; n < 16; n++) {
                    float a = ex2f(dv * cn[n]);
                    h[n] = a * h[n] + u * sB[s0 + s][n];
                    if (n & 1) y1 += h[n] * sC[s0 + s][n];
                    else       y0 += h[n] * sC[s0 + s][n];
                }
                yp[(size_t)(s0 + s) * D_IN] = y0 + y1 + xv * dsv;
            }
        }
    }
}

// ------------------------------- launcher ----------------------------------
extern "C" void kernel_launch(void* const* d_in, const int* in_sizes, int n_in,
                              void* d_out, int out_size)
{
    const float* x     = (const float*)d_in[0];
    const float* gs    = (const float*)d_in[1];
    const float* w1    = (const float*)d_in[2];
    const float* dtw   = (const float*)d_in[3];
    const float* bias  = (const float*)d_in[4];
    const float* alogs = (const float*)d_in[5];
    const float* Ds    = (const float*)d_in[6];
    const float* gcw   = (const float*)d_in[7];
    const float* gcb   = (const float*)d_in[8];
    const float* gCw   = (const float*)d_in[9];
    float* y = (float*)d_out;

    k1a_gemm <<<64 * KSPLIT, 128>>>(x, w1);
    k1b_fused<<<128 * 8, 128>>>(x, dtw, bias, gs, gcw, gcb, gCw, alogs);
    k3_combine<<<BATCH * D_IN, 128>>>(alogs);
    k4_phase3<<<BATCH * 8 * NCHUNK, 128>>>(x, alogs, Ds, y);
}